// round 2
// baseline (speedup 1.0000x reference)
#include <cuda_runtime.h>
#include <cuda_bf16.h>
#include <math.h>

// ---------------- problem constants ----------------
#define NBATCH   2
#define LSEQ     2048
#define TT       4096            // NBATCH*LSEQ tokens
#define DMODEL   1024
#define DINNER   2048
#define DSTATE   16
#define DTRANK   64
#define NEXPERT  8
#define FFND     4096
#define NDBC     96              // DT_RANK + 2*D_STATE
#define MAXR     9216            // 2*TT + 8*64 padding headroom (multiple of 64)

// ---------------- scratch (device globals; no allocation allowed) ----------
__device__ float g_h1 [(size_t)TT * DMODEL];
__device__ float g_xz [(size_t)TT * 2 * DINNER];
__device__ float g_xic[(size_t)TT * DINNER];
__device__ float g_dbc[(size_t)TT * NDBC];
__device__ float g_delta[(size_t)TT * DINNER];
__device__ float g_y2 [(size_t)TT * DINNER];
__device__ float g_h2 [(size_t)TT * DMODEL];
__device__ float g_hn [(size_t)TT * DMODEL];
__device__ int   g_sel[TT * 2];
__device__ float g_wts[TT * 2];
__device__ int   g_cnt[NEXPERT];
__device__ int   g_cur[NEXPERT];
__device__ int   g_seg[NEXPERT + 1];
__device__ int   g_tok[MAXR];
__device__ int   g_rowmap[TT * 2];
__device__ float g_Xg[(size_t)MAXR * DMODEL];
__device__ float g_G [(size_t)MAXR * FFND];
__device__ float g_U [(size_t)MAXR * FFND];
__device__ float g_Y [(size_t)MAXR * DMODEL];

// ---------------- helpers ----------------
__device__ __forceinline__ float siluf(float x) {
    return x / (1.0f + __expf(-x));
}
__device__ __forceinline__ float softplusf(float x) {
    return (x > 20.0f) ? x : log1pf(__expf(x));
}

// ---------------- rmsnorm: one block per row ----------------
__global__ void __launch_bounds__(256) k_rmsnorm(const float* __restrict__ x,
                                                 const float* __restrict__ w,
                                                 float* __restrict__ o)
{
    __shared__ float red[8];
    const int r = blockIdx.x, tid = threadIdx.x;
    const float* xr = x + (size_t)r * DMODEL;
    float s = 0.f;
    #pragma unroll
    for (int i = 0; i < DMODEL / 256; i++) {
        float v = xr[tid + i * 256];
        s += v * v;
    }
    #pragma unroll
    for (int off = 16; off; off >>= 1) s += __shfl_xor_sync(0xffffffff, s, off);
    if ((tid & 31) == 0) red[tid >> 5] = s;
    __syncthreads();
    if (tid < 8) {
        float v = red[tid];
        #pragma unroll
        for (int off = 4; off; off >>= 1) v += __shfl_xor_sync(0xff, v, off);
        if (tid == 0) red[0] = v;
    }
    __syncthreads();
    const float rms = rsqrtf(red[0] * (1.0f / DMODEL) + 1e-5f);
    float* orow = o + (size_t)r * DMODEL;
    #pragma unroll
    for (int i = 0; i < DMODEL / 256; i++) {
        int c = tid + i * 256;
        orow[c] = xr[c] * rms * w[c];
    }
}

// ---------------- generic tiled sgemm: C[M,N] = A[M,K] @ B[K,N] ----------------
// mode 0: plain; mode 1: C = acc + aux (residual, [M,ldc]); mode 2: C = softplus(acc + aux[col])
#define BM 64
#define BN 64
#define BK 16
__global__ void __launch_bounds__(256) k_gemm(const float* __restrict__ A,
                                              const float* __restrict__ B,
                                              float* __restrict__ C,
                                              int M, int N, int K,
                                              int lda, int ldb, int ldc,
                                              int mode, const float* __restrict__ aux)
{
    __shared__ float As[BK][BM];
    __shared__ float Bs[BK][BN];
    const int m0 = blockIdx.y * BM;
    const int n0 = blockIdx.x * BN;
    const int tid = threadIdx.x;
    const int tx = tid & 15, ty = tid >> 4;
    const int arow = tid >> 2, acol = (tid & 3) * 4;
    const int brow = tid >> 4, bcol = (tid & 15) * 4;
    const bool nfull = (n0 + BN <= N);

    float acc[4][4] = {};

    for (int k0 = 0; k0 < K; k0 += BK) {
        float4 av = *reinterpret_cast<const float4*>(A + (size_t)(m0 + arow) * lda + k0 + acol);
        As[acol + 0][arow] = av.x;
        As[acol + 1][arow] = av.y;
        As[acol + 2][arow] = av.z;
        As[acol + 3][arow] = av.w;
        if (nfull) {
            *reinterpret_cast<float4*>(&Bs[brow][bcol]) =
                *reinterpret_cast<const float4*>(B + (size_t)(k0 + brow) * ldb + n0 + bcol);
        } else {
            #pragma unroll
            for (int j = 0; j < 4; j++)
                Bs[brow][bcol + j] = (n0 + bcol + j < N)
                    ? B[(size_t)(k0 + brow) * ldb + n0 + bcol + j] : 0.f;
        }
        __syncthreads();
        #pragma unroll
        for (int k = 0; k < BK; k++) {
            float4 a = *reinterpret_cast<const float4*>(&As[k][ty * 4]);
            float4 b = *reinterpret_cast<const float4*>(&Bs[k][tx * 4]);
            float ar[4] = {a.x, a.y, a.z, a.w};
            float br[4] = {b.x, b.y, b.z, b.w};
            #pragma unroll
            for (int i = 0; i < 4; i++)
                #pragma unroll
                for (int j = 0; j < 4; j++)
                    acc[i][j] += ar[i] * br[j];
        }
        __syncthreads();
    }

    #pragma unroll
    for (int i = 0; i < 4; i++) {
        const int row = m0 + ty * 4 + i;
        #pragma unroll
        for (int j = 0; j < 4; j++) {
            const int col = n0 + tx * 4 + j;
            if (col < N) {
                float v = acc[i][j];
                if (mode == 1) v += aux[(size_t)row * ldc + col];
                else if (mode == 2) v = softplusf(v + aux[col]);
                C[(size_t)row * ldc + col] = v;
            }
        }
    }
}

// ---------------- grouped sgemm over expert segments ----------------
__global__ void __launch_bounds__(256) k_ggemm(const float* __restrict__ A,
                                               const float* __restrict__ Bbase,
                                               float* __restrict__ C,
                                               int N, int K, int lda, int ldb, int ldc,
                                               size_t expStride)
{
    const int m0 = blockIdx.y * BM;
    if (m0 >= g_seg[NEXPERT]) return;
    int e = 0;
    while (g_seg[e + 1] <= m0) e++;
    const float* B = Bbase + (size_t)e * expStride;

    __shared__ float As[BK][BM];
    __shared__ float Bs[BK][BN];
    const int n0 = blockIdx.x * BN;
    const int tid = threadIdx.x;
    const int tx = tid & 15, ty = tid >> 4;
    const int arow = tid >> 2, acol = (tid & 3) * 4;
    const int brow = tid >> 4, bcol = (tid & 15) * 4;

    float acc[4][4] = {};

    for (int k0 = 0; k0 < K; k0 += BK) {
        float4 av = *reinterpret_cast<const float4*>(A + (size_t)(m0 + arow) * lda + k0 + acol);
        As[acol + 0][arow] = av.x;
        As[acol + 1][arow] = av.y;
        As[acol + 2][arow] = av.z;
        As[acol + 3][arow] = av.w;
        *reinterpret_cast<float4*>(&Bs[brow][bcol]) =
            *reinterpret_cast<const float4*>(B + (size_t)(k0 + brow) * ldb + n0 + bcol);
        __syncthreads();
        #pragma unroll
        for (int k = 0; k < BK; k++) {
            float4 a = *reinterpret_cast<const float4*>(&As[k][ty * 4]);
            float4 b = *reinterpret_cast<const float4*>(&Bs[k][tx * 4]);
            float ar[4] = {a.x, a.y, a.z, a.w};
            float br[4] = {b.x, b.y, b.z, b.w};
            #pragma unroll
            for (int i = 0; i < 4; i++)
                #pragma unroll
                for (int j = 0; j < 4; j++)
                    acc[i][j] += ar[i] * br[j];
        }
        __syncthreads();
    }
    #pragma unroll
    for (int i = 0; i < 4; i++)
        #pragma unroll
        for (int j = 0; j < 4; j++)
            C[(size_t)(m0 + ty * 4 + i) * ldc + n0 + tx * 4 + j] = acc[i][j];
}

// ---------------- causal depthwise conv + silu ----------------
__global__ void __launch_bounds__(256) k_conv(const float* __restrict__ cw,
                                              const float* __restrict__ cb)
{
    const int idx = blockIdx.x * 256 + threadIdx.x;   // over TT*DINNER
    const int c = idx & (DINNER - 1);
    const int tg = idx >> 11;                          // token index
    const int l = tg & (LSEQ - 1);
    float acc = cb[c];
    #pragma unroll
    for (int k = 0; k < 4; k++) {
        const int dl = l - 3 + k;
        if (dl >= 0)
            acc += cw[c * 4 + k] * g_xz[(size_t)(tg - 3 + k) * (2 * DINNER) + c];
    }
    g_xic[(size_t)tg * DINNER + c] = siluf(acc);
}

// ---------------- selective scan: 16 channels/block, 16 lanes/channel --------
__global__ void __launch_bounds__(256) k_scan(const float* __restrict__ A_log,
                                              const float* __restrict__ D_skip)
{
    const int b = blockIdx.x >> 7;               // batch
    const int cg = blockIdx.x & 127;             // channel group
    const int tid = threadIdx.x;
    const int c = cg * 16 + (tid >> 4);
    const int n = tid & 15;

    const float A = -__expf(A_log[c * DSTATE + n]);
    const float D = D_skip[c];
    float h = 0.f;

    const float* dlt = g_delta + (size_t)b * LSEQ * DINNER + c;
    const float* xin = g_xic   + (size_t)b * LSEQ * DINNER + c;
    const float* dbc = g_dbc   + (size_t)b * LSEQ * NDBC;
    const float* zin = g_xz    + (size_t)b * LSEQ * (2 * DINNER) + DINNER + c;
    float* yout = g_y2 + (size_t)b * LSEQ * DINNER + c;

    for (int l = 0; l < LSEQ; l++) {
        const float d  = dlt[(size_t)l * DINNER];
        const float x  = xin[(size_t)l * DINNER];
        const float Bn = dbc[(size_t)l * NDBC + DTRANK + n];
        const float Cn = dbc[(size_t)l * NDBC + DTRANK + DSTATE + n];
        const float dA = __expf(d * A);
        h = dA * h + (d * x) * Bn;
        float v = h * Cn;
        v += __shfl_xor_sync(0xffffffff, v, 1);
        v += __shfl_xor_sync(0xffffffff, v, 2);
        v += __shfl_xor_sync(0xffffffff, v, 4);
        v += __shfl_xor_sync(0xffffffff, v, 8);
        if (n == 0) {
            const float z = zin[(size_t)l * (2 * DINNER)];
            yout[(size_t)l * DINNER] = (v + D * x) * siluf(z);
        }
    }
}

// ---------------- router: one warp per token, softmax + top2 ----------------
__global__ void k_zero8() { if (threadIdx.x < NEXPERT) g_cnt[threadIdx.x] = 0; }

__global__ void __launch_bounds__(256) k_router(const float* __restrict__ rw)
{
    const int warp = threadIdx.x >> 5, lane = threadIdx.x & 31;
    const int t = blockIdx.x * 8 + warp;
    const float* hrow = g_hn + (size_t)t * DMODEL;
    float acc[NEXPERT] = {};
    for (int d = lane; d < DMODEL; d += 32) {
        const float h = hrow[d];
        #pragma unroll
        for (int e = 0; e < NEXPERT; e++) acc[e] += h * rw[d * NEXPERT + e];
    }
    #pragma unroll
    for (int off = 16; off; off >>= 1)
        #pragma unroll
        for (int e = 0; e < NEXPERT; e++)
            acc[e] += __shfl_xor_sync(0xffffffff, acc[e], off);
    if (lane == 0) {
        float m = acc[0];
        #pragma unroll
        for (int e = 1; e < NEXPERT; e++) m = fmaxf(m, acc[e]);
        float p[NEXPERT], s = 0.f;
        #pragma unroll
        for (int e = 0; e < NEXPERT; e++) { p[e] = __expf(acc[e] - m); s += p[e]; }
        const float inv = 1.0f / s;
        #pragma unroll
        for (int e = 0; e < NEXPERT; e++) p[e] *= inv;
        int i1 = 0;
        #pragma unroll
        for (int e = 1; e < NEXPERT; e++) if (p[e] > p[i1]) i1 = e;
        int i2 = (i1 == 0) ? 1 : 0;
        #pragma unroll
        for (int e = 0; e < NEXPERT; e++) if (e != i1 && p[e] > p[i2]) i2 = e;
        g_sel[t * 2] = i1; g_sel[t * 2 + 1] = i2;
        g_wts[t * 2] = p[i1]; g_wts[t * 2 + 1] = p[i2];
        atomicAdd(&g_cnt[i1], 1);
        atomicAdd(&g_cnt[i2], 1);
    }
}

__global__ void k_seg()
{
    int s = 0;
    g_seg[0] = 0;
    for (int e = 0; e < NEXPERT; e++) {
        g_cur[e] = s;
        s += ((g_cnt[e] + BM - 1) / BM) * BM;
        g_seg[e + 1] = s;
    }
}

__global__ void __launch_bounds__(256) k_assign()
{
    const int idx = blockIdx.x * 256 + threadIdx.x;   // over TT*2
    const int e = g_sel[idx];
    const int r = atomicAdd(&g_cur[e], 1);
    g_tok[r] = idx >> 1;
    g_rowmap[idx] = r;
}

__global__ void __launch_bounds__(256) k_gather()
{
    const int row = blockIdx.x;
    if (row >= g_seg[NEXPERT]) return;
    const float* src = g_hn + (size_t)g_tok[row] * DMODEL;
    float* dst = g_Xg + (size_t)row * DMODEL;
    const int c = threadIdx.x * 4;
    *reinterpret_cast<float4*>(dst + c) = *reinterpret_cast<const float4*>(src + c);
}

__global__ void __launch_bounds__(256) k_glu()
{
    const int row = blockIdx.x;
    if (row >= g_seg[NEXPERT]) return;
    float* grow = g_G + (size_t)row * FFND;
    const float* urow = g_U + (size_t)row * FFND;
    #pragma unroll
    for (int i = 0; i < FFND / 256; i++) {
        const int c = threadIdx.x + i * 256;
        grow[c] = siluf(grow[c]) * urow[c];
    }
}

__global__ void __launch_bounds__(256) k_combine(float* __restrict__ out)
{
    const int t = blockIdx.x;
    const int r0 = g_rowmap[t * 2], r1 = g_rowmap[t * 2 + 1];
    const float w0 = g_wts[t * 2], w1 = g_wts[t * 2 + 1];
    const int c = threadIdx.x * 4;
    float4 a = *reinterpret_cast<const float4*>(g_h2 + (size_t)t * DMODEL + c);
    float4 y0 = *reinterpret_cast<const float4*>(g_Y + (size_t)r0 * DMODEL + c);
    float4 y1 = *reinterpret_cast<const float4*>(g_Y + (size_t)r1 * DMODEL + c);
    a.x += w0 * y0.x + w1 * y1.x;
    a.y += w0 * y0.y + w1 * y1.y;
    a.z += w0 * y0.z + w1 * y1.z;
    a.w += w0 * y0.w + w1 * y1.w;
    *reinterpret_cast<float4*>(out + (size_t)t * DMODEL + c) = a;
}

// ---------------- launch ----------------
extern "C" void kernel_launch(void* const* d_in, const int* in_sizes, int n_in,
                              void* d_out, int out_size)
{
    const float* x          = (const float*)d_in[0];
    const float* rms1_w     = (const float*)d_in[1];
    const float* rms2_w     = (const float*)d_in[2];
    const float* in_proj_w  = (const float*)d_in[3];
    const float* conv_w     = (const float*)d_in[4];
    const float* conv_b     = (const float*)d_in[5];
    const float* x_proj_w   = (const float*)d_in[6];
    const float* dt_proj_w  = (const float*)d_in[7];
    const float* dt_proj_b  = (const float*)d_in[8];
    const float* A_log      = (const float*)d_in[9];
    const float* D_skip     = (const float*)d_in[10];
    const float* out_proj_w = (const float*)d_in[11];
    const float* router_w   = (const float*)d_in[12];
    const float* Wg         = (const float*)d_in[13];
    const float* Wu         = (const float*)d_in[14];
    const float* Wd         = (const float*)d_in[15];
    float* out = (float*)d_out;

    float *p_h1, *p_xz, *p_xic, *p_dbc, *p_delta, *p_y2, *p_h2, *p_hn;
    float *p_Xg, *p_G, *p_U, *p_Y;
    cudaGetSymbolAddress((void**)&p_h1, g_h1);
    cudaGetSymbolAddress((void**)&p_xz, g_xz);
    cudaGetSymbolAddress((void**)&p_xic, g_xic);
    cudaGetSymbolAddress((void**)&p_dbc, g_dbc);
    cudaGetSymbolAddress((void**)&p_delta, g_delta);
    cudaGetSymbolAddress((void**)&p_y2, g_y2);
    cudaGetSymbolAddress((void**)&p_h2, g_h2);
    cudaGetSymbolAddress((void**)&p_hn, g_hn);
    cudaGetSymbolAddress((void**)&p_Xg, g_Xg);
    cudaGetSymbolAddress((void**)&p_G, g_G);
    cudaGetSymbolAddress((void**)&p_U, g_U);
    cudaGetSymbolAddress((void**)&p_Y, g_Y);

    // 1. rmsnorm1
    k_rmsnorm<<<TT, 256>>>(x, rms1_w, p_h1);
    // 2. in_proj: [TT,1024] @ [1024,4096]
    k_gemm<<<dim3(2 * DINNER / BN, TT / BM), 256>>>(p_h1, in_proj_w, p_xz,
        TT, 2 * DINNER, DMODEL, DMODEL, 2 * DINNER, 2 * DINNER, 0, nullptr);
    // 3. depthwise conv + silu
    k_conv<<<TT * DINNER / 256, 256>>>(conv_w, conv_b);
    // 4. x_proj: [TT,2048] @ [2048,96]
    k_gemm<<<dim3((NDBC + BN - 1) / BN, TT / BM), 256>>>(p_xic, x_proj_w, p_dbc,
        TT, NDBC, DINNER, DINNER, NDBC, NDBC, 0, nullptr);
    // 5. dt_proj + softplus: [TT,64] @ [64,2048]
    k_gemm<<<dim3(DINNER / BN, TT / BM), 256>>>(p_dbc, dt_proj_w, p_delta,
        TT, DINNER, DTRANK, NDBC, DINNER, DINNER, 2, dt_proj_b);
    // 6. selective scan + gating
    k_scan<<<NBATCH * (DINNER / 16), 256>>>(A_log, D_skip);
    // 7. out_proj + residual: [TT,2048] @ [2048,1024] + x
    k_gemm<<<dim3(DMODEL / BN, TT / BM), 256>>>(p_y2, out_proj_w, p_h2,
        TT, DMODEL, DINNER, DINNER, DMODEL, DMODEL, 1, x);
    // 8. rmsnorm2
    k_rmsnorm<<<TT, 256>>>(p_h2, rms2_w, p_hn);
    // 9-12. router + expert sort
    k_zero8<<<1, 32>>>();
    k_router<<<TT / 8, 256>>>(router_w);
    k_seg<<<1, 1>>>();
    k_assign<<<TT * 2 / 256, 256>>>();
    k_gather<<<MAXR, 256>>>();
    // 13-15. MoE grouped GEMMs
    k_ggemm<<<dim3(FFND / BN, MAXR / BM), 256>>>(p_Xg, Wg, p_G,
        FFND, DMODEL, DMODEL, FFND, FFND, (size_t)DMODEL * FFND);
    k_ggemm<<<dim3(FFND / BN, MAXR / BM), 256>>>(p_Xg, Wu, p_U,
        FFND, DMODEL, DMODEL, FFND, FFND, (size_t)DMODEL * FFND);
    k_glu<<<MAXR, 256>>>();
    k_ggemm<<<dim3(DMODEL / BN, MAXR / BM), 256>>>(p_G, Wd, p_Y,
        DMODEL, FFND, FFND, DMODEL, DMODEL, (size_t)FFND * DMODEL);
    // 16. combine + residual -> out
    k_combine<<<TT, 256>>>(out);
}

// round 3
// speedup vs baseline: 2.4182x; 2.4182x over previous
#include <cuda_runtime.h>
#include <cuda_bf16.h>
#include <math.h>

// ---------------- problem constants ----------------
#define NBATCH   2
#define LSEQ     2048
#define TT       4096            // NBATCH*LSEQ tokens
#define DMODEL   1024
#define DINNER   2048
#define DSTATE   16
#define DTRANK   64
#define NEXPERT  8
#define FFND     4096
#define LDDBC    128             // padded DT_RANK + 2*D_STATE (96 -> 128)
#define MAXR     9216            // 2*TT + 8*128 padding headroom (multiple of 128)

// ---------------- scratch (device globals; no allocation allowed) ----------
__device__ float g_h1 [(size_t)TT * DMODEL];
__device__ float g_xz [(size_t)TT * 2 * DINNER];
__device__ float g_xic[(size_t)TT * DINNER];
__device__ float g_dbc[(size_t)TT * LDDBC];
__device__ float g_xpw[(size_t)DINNER * LDDBC];   // padded x_proj_w
__device__ float g_delta[(size_t)TT * DINNER];
__device__ float g_y2 [(size_t)TT * DINNER];
__device__ float g_h2 [(size_t)TT * DMODEL];
__device__ float g_hn [(size_t)TT * DMODEL];
__device__ int   g_sel[TT * 2];
__device__ float g_wts[TT * 2];
__device__ int   g_cnt[NEXPERT];
__device__ int   g_cur[NEXPERT];
__device__ int   g_seg[NEXPERT + 1];
__device__ int   g_tok[MAXR];
__device__ int   g_rowmap[TT * 2];
__device__ float g_Xg[(size_t)MAXR * DMODEL];
__device__ float g_G [(size_t)MAXR * FFND];
__device__ float g_U [(size_t)MAXR * FFND];
__device__ float g_Y [(size_t)MAXR * DMODEL];

// ---------------- helpers ----------------
__device__ __forceinline__ float siluf(float x) {
    return x / (1.0f + __expf(-x));
}
__device__ __forceinline__ float softplusf(float x) {
    return (x > 20.0f) ? x : log1pf(__expf(x));
}
__device__ __forceinline__ void cp_async16(void* sp, const void* gp) {
    unsigned s = (unsigned)__cvta_generic_to_shared(sp);
    asm volatile("cp.async.cg.shared.global [%0], [%1], 16;\n" :: "r"(s), "l"(gp));
}
__device__ __forceinline__ void mma_tf32(float* c, const unsigned* a, const unsigned* b) {
    asm volatile(
        "mma.sync.aligned.m16n8k8.row.col.f32.tf32.tf32.f32 "
        "{%0,%1,%2,%3},{%4,%5,%6,%7},{%8,%9},{%0,%1,%2,%3};\n"
        : "+f"(c[0]), "+f"(c[1]), "+f"(c[2]), "+f"(c[3])
        : "r"(a[0]), "r"(a[1]), "r"(a[2]), "r"(a[3]), "r"(b[0]), "r"(b[1]));
}

// ---------------- rmsnorm: one block per row ----------------
__global__ void __launch_bounds__(256) k_rmsnorm(const float* __restrict__ x,
                                                 const float* __restrict__ w,
                                                 float* __restrict__ o)
{
    __shared__ float red[8];
    const int r = blockIdx.x, tid = threadIdx.x;
    const float* xr = x + (size_t)r * DMODEL;
    float s = 0.f;
    #pragma unroll
    for (int i = 0; i < DMODEL / 256; i++) {
        float v = xr[tid + i * 256];
        s += v * v;
    }
    #pragma unroll
    for (int off = 16; off; off >>= 1) s += __shfl_xor_sync(0xffffffff, s, off);
    if ((tid & 31) == 0) red[tid >> 5] = s;
    __syncthreads();
    if (tid < 8) {
        float v = red[tid];
        #pragma unroll
        for (int off = 4; off; off >>= 1) v += __shfl_xor_sync(0xff, v, off);
        if (tid == 0) red[0] = v;
    }
    __syncthreads();
    const float rms = rsqrtf(red[0] * (1.0f / DMODEL) + 1e-5f);
    float* orow = o + (size_t)r * DMODEL;
    #pragma unroll
    for (int i = 0; i < DMODEL / 256; i++) {
        int c = tid + i * 256;
        orow[c] = xr[c] * rms * w[c];
    }
}

// ---------------- tf32 tensor-core GEMM ----------------
// C[M,N] = A[M,K] @ B[K,N]; tiles 128x128x32, 8 warps, cp.async double buffer.
// Requires M%128==0 (grouped: padded segs), N%128==0, K%32==0, all ptrs 16B-aligned,
// lda/ldb/ldc multiples of 4.
// mode 0: plain; 1: C = acc + aux[row*ldc+col]; 2: C = softplus(acc + aux[col])
#define TBM 128
#define TBN 128
#define TBK 32
#define ASTR 36            // TBK + 4   (A stored [m][k])
#define BSTR 136           // TBN + 8   (B stored [k][n])
#define AS_STAGE (TBM * ASTR)      // 4608 floats
#define BS_STAGE (TBK * BSTR)      // 4352 floats
#define MMA_SMEM_BYTES (2 * (AS_STAGE + BS_STAGE) * 4)   // 71680

__global__ void __launch_bounds__(256) k_mma(const float* __restrict__ A,
                                             const float* __restrict__ Bbase,
                                             float* __restrict__ C,
                                             int M, int N, int K,
                                             int lda, int ldb, int ldc,
                                             int mode, const float* __restrict__ aux,
                                             int grouped, size_t expStride)
{
    const int m0 = blockIdx.y * TBM;
    const int n0 = blockIdx.x * TBN;
    const float* B = Bbase;
    if (grouped) {
        if (m0 >= g_seg[NEXPERT]) return;
        int e = 0;
        while (g_seg[e + 1] <= m0) e++;
        B += (size_t)e * expStride;
    }

    extern __shared__ float sm[];
    float* As = sm;                       // [2][TBM][ASTR]
    float* Bs = sm + 2 * AS_STAGE;        // [2][TBK][BSTR]

    const int tid = threadIdx.x;
    const int wid = tid >> 5, lane = tid & 31;
    const int wm = (wid >> 2) * 64;       // warp m offset in tile
    const int wn = (wid & 3) * 32;        // warp n offset in tile
    const int lr = lane >> 2;             // 0..7
    const int lc = lane & 3;              // 0..3

    float acc[4][4][4];
    #pragma unroll
    for (int i = 0; i < 4; i++)
        #pragma unroll
        for (int j = 0; j < 4; j++)
            #pragma unroll
            for (int r = 0; r < 4; r++) acc[i][j][r] = 0.f;

    // per-thread load coordinates (4 x 16B chunks per tile per matrix)
    const int nIter = K / TBK;

    auto issue = [&](int st, int k0) {
        #pragma unroll
        for (int w = 0; w < 4; w++) {
            const int id = tid + w * 256;
            const int ar = id >> 3, akc = (id & 7) * 4;
            cp_async16(&As[st * AS_STAGE + ar * ASTR + akc],
                       A + (size_t)(m0 + ar) * lda + k0 + akc);
            const int bk = id >> 5, bn = (id & 31) * 4;
            cp_async16(&Bs[st * BS_STAGE + bk * BSTR + bn],
                       B + (size_t)(k0 + bk) * ldb + n0 + bn);
        }
        asm volatile("cp.async.commit_group;\n" ::);
    };

    issue(0, 0);

    for (int it = 0; it < nIter; it++) {
        if (it + 1 < nIter) {
            issue((it + 1) & 1, (it + 1) * TBK);
            asm volatile("cp.async.wait_group 1;\n" ::);
        } else {
            asm volatile("cp.async.wait_group 0;\n" ::);
        }
        __syncthreads();

        const float* Ab = &As[(it & 1) * AS_STAGE];
        const float* Bb = &Bs[(it & 1) * BS_STAGE];
        #pragma unroll
        for (int ks = 0; ks < 4; ks++) {
            const int kb = ks * 8;
            unsigned a[4][4], b[4][2];
            #pragma unroll
            for (int mt = 0; mt < 4; mt++) {
                const int row = wm + mt * 16 + lr;
                a[mt][0] = __float_as_uint(Ab[row * ASTR + kb + lc]);
                a[mt][1] = __float_as_uint(Ab[(row + 8) * ASTR + kb + lc]);
                a[mt][2] = __float_as_uint(Ab[row * ASTR + kb + lc + 4]);
                a[mt][3] = __float_as_uint(Ab[(row + 8) * ASTR + kb + lc + 4]);
            }
            #pragma unroll
            for (int nt = 0; nt < 4; nt++) {
                const int col = wn + nt * 8 + lr;
                b[nt][0] = __float_as_uint(Bb[(kb + lc) * BSTR + col]);
                b[nt][1] = __float_as_uint(Bb[(kb + lc + 4) * BSTR + col]);
            }
            #pragma unroll
            for (int mt = 0; mt < 4; mt++)
                #pragma unroll
                for (int nt = 0; nt < 4; nt++)
                    mma_tf32(acc[mt][nt], a[mt], b[nt]);
        }
        __syncthreads();
    }

    // epilogue
    #pragma unroll
    for (int mt = 0; mt < 4; mt++) {
        #pragma unroll
        for (int nt = 0; nt < 4; nt++) {
            const int row = m0 + wm + mt * 16 + lr;
            const int col = n0 + wn + nt * 8 + lc * 2;
            float2 v0 = make_float2(acc[mt][nt][0], acc[mt][nt][1]);   // row
            float2 v1 = make_float2(acc[mt][nt][2], acc[mt][nt][3]);   // row+8
            if (mode == 1) {
                const float2 r0 = *reinterpret_cast<const float2*>(aux + (size_t)row * ldc + col);
                const float2 r1 = *reinterpret_cast<const float2*>(aux + (size_t)(row + 8) * ldc + col);
                v0.x += r0.x; v0.y += r0.y;
                v1.x += r1.x; v1.y += r1.y;
            } else if (mode == 2) {
                const float b0 = aux[col], b1 = aux[col + 1];
                v0.x = softplusf(v0.x + b0); v0.y = softplusf(v0.y + b1);
                v1.x = softplusf(v1.x + b0); v1.y = softplusf(v1.y + b1);
            }
            *reinterpret_cast<float2*>(C + (size_t)row * ldc + col) = v0;
            *reinterpret_cast<float2*>(C + (size_t)(row + 8) * ldc + col) = v1;
        }
    }
}

// ---------------- pad x_proj_w [2048,96] -> g_xpw [2048,128] ----------------
__global__ void __launch_bounds__(256) k_padw(const float* __restrict__ w)
{
    const int i = blockIdx.x * 256 + threadIdx.x;   // over DINNER*128
    const int k = i >> 7, n = i & 127;
    g_xpw[i] = (n < 96) ? w[k * 96 + n] : 0.f;
}

// ---------------- causal depthwise conv + silu ----------------
__global__ void __launch_bounds__(256) k_conv(const float* __restrict__ cw,
                                              const float* __restrict__ cb)
{
    const int idx = blockIdx.x * 256 + threadIdx.x;   // over TT*DINNER
    const int c = idx & (DINNER - 1);
    const int tg = idx >> 11;                          // token index
    const int l = tg & (LSEQ - 1);
    float acc = cb[c];
    #pragma unroll
    for (int k = 0; k < 4; k++) {
        const int dl = l - 3 + k;
        if (dl >= 0)
            acc += cw[c * 4 + k] * g_xz[(size_t)(tg - 3 + k) * (2 * DINNER) + c];
    }
    g_xic[(size_t)tg * DINNER + c] = siluf(acc);
}

// ---------------- selective scan: 16 channels/block, 16 lanes/channel --------
__global__ void __launch_bounds__(256) k_scan(const float* __restrict__ A_log,
                                              const float* __restrict__ D_skip)
{
    const int b = blockIdx.x >> 7;               // batch
    const int cg = blockIdx.x & 127;             // channel group
    const int tid = threadIdx.x;
    const int c = cg * 16 + (tid >> 4);
    const int n = tid & 15;

    const float A = -__expf(A_log[c * DSTATE + n]);
    const float D = D_skip[c];
    float h = 0.f;

    const float* dlt = g_delta + (size_t)b * LSEQ * DINNER + c;
    const float* xin = g_xic   + (size_t)b * LSEQ * DINNER + c;
    const float* dbc = g_dbc   + (size_t)b * LSEQ * LDDBC;
    const float* zin = g_xz    + (size_t)b * LSEQ * (2 * DINNER) + DINNER + c;
    float* yout = g_y2 + (size_t)b * LSEQ * DINNER + c;

    for (int l = 0; l < LSEQ; l++) {
        const float d  = dlt[(size_t)l * DINNER];
        const float x  = xin[(size_t)l * DINNER];
        const float Bn = dbc[(size_t)l * LDDBC + DTRANK + n];
        const float Cn = dbc[(size_t)l * LDDBC + DTRANK + DSTATE + n];
        const float dA = __expf(d * A);
        h = dA * h + (d * x) * Bn;
        float v = h * Cn;
        v += __shfl_xor_sync(0xffffffff, v, 1);
        v += __shfl_xor_sync(0xffffffff, v, 2);
        v += __shfl_xor_sync(0xffffffff, v, 4);
        v += __shfl_xor_sync(0xffffffff, v, 8);
        if (n == 0) {
            const float z = zin[(size_t)l * (2 * DINNER)];
            yout[(size_t)l * DINNER] = (v + D * x) * siluf(z);
        }
    }
}

// ---------------- router: one warp per token, softmax + top2 ----------------
__global__ void k_zero8() { if (threadIdx.x < NEXPERT) g_cnt[threadIdx.x] = 0; }

__global__ void __launch_bounds__(256) k_router(const float* __restrict__ rw)
{
    const int warp = threadIdx.x >> 5, lane = threadIdx.x & 31;
    const int t = blockIdx.x * 8 + warp;
    const float* hrow = g_hn + (size_t)t * DMODEL;
    float acc[NEXPERT] = {};
    for (int d = lane; d < DMODEL; d += 32) {
        const float h = hrow[d];
        #pragma unroll
        for (int e = 0; e < NEXPERT; e++) acc[e] += h * rw[d * NEXPERT + e];
    }
    #pragma unroll
    for (int off = 16; off; off >>= 1)
        #pragma unroll
        for (int e = 0; e < NEXPERT; e++)
            acc[e] += __shfl_xor_sync(0xffffffff, acc[e], off);
    if (lane == 0) {
        float m = acc[0];
        #pragma unroll
        for (int e = 1; e < NEXPERT; e++) m = fmaxf(m, acc[e]);
        float p[NEXPERT], s = 0.f;
        #pragma unroll
        for (int e = 0; e < NEXPERT; e++) { p[e] = __expf(acc[e] - m); s += p[e]; }
        const float inv = 1.0f / s;
        #pragma unroll
        for (int e = 0; e < NEXPERT; e++) p[e] *= inv;
        int i1 = 0;
        #pragma unroll
        for (int e = 1; e < NEXPERT; e++) if (p[e] > p[i1]) i1 = e;
        int i2 = (i1 == 0) ? 1 : 0;
        #pragma unroll
        for (int e = 0; e < NEXPERT; e++) if (e != i1 && p[e] > p[i2]) i2 = e;
        g_sel[t * 2] = i1; g_sel[t * 2 + 1] = i2;
        g_wts[t * 2] = p[i1]; g_wts[t * 2 + 1] = p[i2];
        atomicAdd(&g_cnt[i1], 1);
        atomicAdd(&g_cnt[i2], 1);
    }
}

__global__ void k_seg()
{
    int s = 0;
    g_seg[0] = 0;
    for (int e = 0; e < NEXPERT; e++) {
        g_cur[e] = s;
        s += ((g_cnt[e] + TBM - 1) / TBM) * TBM;
        g_seg[e + 1] = s;
    }
}

__global__ void __launch_bounds__(256) k_assign()
{
    const int idx = blockIdx.x * 256 + threadIdx.x;   // over TT*2
    const int e = g_sel[idx];
    const int r = atomicAdd(&g_cur[e], 1);
    g_tok[r] = idx >> 1;
    g_rowmap[idx] = r;
}

__global__ void __launch_bounds__(256) k_gather()
{
    const int row = blockIdx.x;
    if (row >= g_seg[NEXPERT]) return;
    int e = 0;
    while (g_seg[e + 1] <= row) e++;
    float* dst = g_Xg + (size_t)row * DMODEL;
    const int c = threadIdx.x * 4;
    if (row >= g_cur[e]) {   // padding row -> zero
        *reinterpret_cast<float4*>(dst + c) = make_float4(0.f, 0.f, 0.f, 0.f);
        return;
    }
    const float* src = g_hn + (size_t)g_tok[row] * DMODEL;
    *reinterpret_cast<float4*>(dst + c) = *reinterpret_cast<const float4*>(src + c);
}

__global__ void __launch_bounds__(256) k_glu()
{
    const int row = blockIdx.x;
    if (row >= g_seg[NEXPERT]) return;
    float* grow = g_G + (size_t)row * FFND;
    const float* urow = g_U + (size_t)row * FFND;
    #pragma unroll
    for (int i = 0; i < FFND / 256; i++) {
        const int c = threadIdx.x + i * 256;
        grow[c] = siluf(grow[c]) * urow[c];
    }
}

__global__ void __launch_bounds__(256) k_combine(float* __restrict__ out)
{
    const int t = blockIdx.x;
    const int r0 = g_rowmap[t * 2], r1 = g_rowmap[t * 2 + 1];
    const float w0 = g_wts[t * 2], w1 = g_wts[t * 2 + 1];
    const int c = threadIdx.x * 4;
    float4 a = *reinterpret_cast<const float4*>(g_h2 + (size_t)t * DMODEL + c);
    float4 y0 = *reinterpret_cast<const float4*>(g_Y + (size_t)r0 * DMODEL + c);
    float4 y1 = *reinterpret_cast<const float4*>(g_Y + (size_t)r1 * DMODEL + c);
    a.x += w0 * y0.x + w1 * y1.x;
    a.y += w0 * y0.y + w1 * y1.y;
    a.z += w0 * y0.z + w1 * y1.z;
    a.w += w0 * y0.w + w1 * y1.w;
    *reinterpret_cast<float4*>(out + (size_t)t * DMODEL + c) = a;
}

// ---------------- launch ----------------
extern "C" void kernel_launch(void* const* d_in, const int* in_sizes, int n_in,
                              void* d_out, int out_size)
{
    const float* x          = (const float*)d_in[0];
    const float* rms1_w     = (const float*)d_in[1];
    const float* rms2_w     = (const float*)d_in[2];
    const float* in_proj_w  = (const float*)d_in[3];
    const float* conv_w     = (const float*)d_in[4];
    const float* conv_b     = (const float*)d_in[5];
    const float* x_proj_w   = (const float*)d_in[6];
    const float* dt_proj_w  = (const float*)d_in[7];
    const float* dt_proj_b  = (const float*)d_in[8];
    const float* A_log      = (const float*)d_in[9];
    const float* D_skip     = (const float*)d_in[10];
    const float* out_proj_w = (const float*)d_in[11];
    const float* router_w   = (const float*)d_in[12];
    const float* Wg         = (const float*)d_in[13];
    const float* Wu         = (const float*)d_in[14];
    const float* Wd         = (const float*)d_in[15];
    float* out = (float*)d_out;

    static int smem_set = 0;
    if (!smem_set) {
        cudaFuncSetAttribute(k_mma, cudaFuncAttributeMaxDynamicSharedMemorySize,
                             MMA_SMEM_BYTES);
        smem_set = 1;
    }

    float *p_h1, *p_xz, *p_xic, *p_dbc, *p_xpw, *p_delta, *p_y2, *p_h2, *p_hn;
    float *p_Xg, *p_G, *p_U, *p_Y;
    cudaGetSymbolAddress((void**)&p_h1, g_h1);
    cudaGetSymbolAddress((void**)&p_xz, g_xz);
    cudaGetSymbolAddress((void**)&p_xic, g_xic);
    cudaGetSymbolAddress((void**)&p_dbc, g_dbc);
    cudaGetSymbolAddress((void**)&p_xpw, g_xpw);
    cudaGetSymbolAddress((void**)&p_delta, g_delta);
    cudaGetSymbolAddress((void**)&p_y2, g_y2);
    cudaGetSymbolAddress((void**)&p_h2, g_h2);
    cudaGetSymbolAddress((void**)&p_hn, g_hn);
    cudaGetSymbolAddress((void**)&p_Xg, g_Xg);
    cudaGetSymbolAddress((void**)&p_G, g_G);
    cudaGetSymbolAddress((void**)&p_U, g_U);
    cudaGetSymbolAddress((void**)&p_Y, g_Y);

    // 0. pad x_proj weight (independent)
    k_padw<<<DINNER * LDDBC / 256, 256>>>(x_proj_w);
    // 1. rmsnorm1
    k_rmsnorm<<<TT, 256>>>(x, rms1_w, p_h1);
    // 2. in_proj: [TT,1024] @ [1024,4096]
    k_mma<<<dim3(2 * DINNER / TBN, TT / TBM), 256, MMA_SMEM_BYTES>>>(
        p_h1, in_proj_w, p_xz, TT, 2 * DINNER, DMODEL,
        DMODEL, 2 * DINNER, 2 * DINNER, 0, nullptr, 0, 0);
    // 3. depthwise conv + silu
    k_conv<<<TT * DINNER / 256, 256>>>(conv_w, conv_b);
    // 4. x_proj (padded): [TT,2048] @ [2048,128]
    k_mma<<<dim3(LDDBC / TBN, TT / TBM), 256, MMA_SMEM_BYTES>>>(
        p_xic, p_xpw, p_dbc, TT, LDDBC, DINNER,
        DINNER, LDDBC, LDDBC, 0, nullptr, 0, 0);
    // 5. dt_proj + softplus: [TT,64] @ [64,2048]
    k_mma<<<dim3(DINNER / TBN, TT / TBM), 256, MMA_SMEM_BYTES>>>(
        p_dbc, dt_proj_w, p_delta, TT, DINNER, DTRANK,
        LDDBC, DINNER, DINNER, 2, dt_proj_b, 0, 0);
    // 6. selective scan + gating
    k_scan<<<NBATCH * (DINNER / 16), 256>>>(A_log, D_skip);
    // 7. out_proj + residual: [TT,2048] @ [2048,1024] + x
    k_mma<<<dim3(DMODEL / TBN, TT / TBM), 256, MMA_SMEM_BYTES>>>(
        p_y2, out_proj_w, p_h2, TT, DMODEL, DINNER,
        DINNER, DMODEL, DMODEL, 1, x, 0, 0);
    // 8. rmsnorm2
    k_rmsnorm<<<TT, 256>>>(p_h2, rms2_w, p_hn);
    // 9-12. router + expert sort
    k_zero8<<<1, 32>>>();
    k_router<<<TT / 8, 256>>>(router_w);
    k_seg<<<1, 1>>>();
    k_assign<<<TT * 2 / 256, 256>>>();
    k_gather<<<MAXR, 256>>>();
    // 13-15. MoE grouped GEMMs
    k_mma<<<dim3(FFND / TBN, MAXR / TBM), 256, MMA_SMEM_BYTES>>>(
        p_Xg, Wg, p_G, MAXR, FFND, DMODEL,
        DMODEL, FFND, FFND, 0, nullptr, 1, (size_t)DMODEL * FFND);
    k_mma<<<dim3(FFND / TBN, MAXR / TBM), 256, MMA_SMEM_BYTES>>>(
        p_Xg, Wu, p_U, MAXR, FFND, DMODEL,
        DMODEL, FFND, FFND, 0, nullptr, 1, (size_t)DMODEL * FFND);
    k_glu<<<MAXR, 256>>>();
    k_mma<<<dim3(DMODEL / TBN, MAXR / TBM), 256, MMA_SMEM_BYTES>>>(
        p_G, Wd, p_Y, MAXR, DMODEL, FFND,
        FFND, DMODEL, DMODEL, 0, nullptr, 1, (size_t)FFND * DMODEL);
    // 16. combine + residual -> out
    k_combine<<<TT, 256>>>(out);
}